// round 2
// baseline (speedup 1.0000x reference)
#include <cuda_runtime.h>

// SudokuIterate: one fused kernel, one block per board.
//
// Inputs (metadata order):
//   d_in[0] sudoku          [B,9,9,9] f32   (B*729 elems)
//   d_in[1] recursion_mask  [B,9,9,9] f32
//   d_in[2] recursion_index [B,1,1,1] f32   (B elems)
//   d_in[3] conv_w          [1,9,1,1] f32   (9 elems)
//   d_in[4] conv_b          [1]       f32
// Output: concat(sudoku_out [B*729], recursion_mask_out [B*729], recursion_index+1 [B])

#define KDIM    9
#define CELLS   81
#define ELEMS   729
#define THREADS 128

// Monotone map fp32 -> uint32 (preserves total order incl. negatives)
__device__ __forceinline__ unsigned int fmap(float f) {
    unsigned int u = __float_as_uint(f);
    return (u & 0x80000000u) ? ~u : (u | 0x80000000u);
}

__global__ __launch_bounds__(THREADS)
void sudoku_iterate_kernel(const float* __restrict__ sud,
                           const float* __restrict__ rmask,
                           const float* __restrict__ rindex,
                           const float* __restrict__ conv_w,
                           const float* __restrict__ conv_b,
                           float* __restrict__ out,
                           int B) {
    __shared__ float s[ELEMS];
    __shared__ float w[KDIM];
    __shared__ unsigned long long keys[THREADS];
    __shared__ int   sh_cell, sh_midx;
    __shared__ float sh_mval, sh_cm_star, sh_cb_clip;

    const int b = blockIdx.x;
    const int t = threadIdx.x;
    const float* __restrict__ sb = sud   + (size_t)b * ELEMS;
    const float* __restrict__ rb = rmask + (size_t)b * ELEMS;

    if (t < KDIM) w[t] = conv_w[t];
    const float cb = conv_b[0];

    // Stage the board into shared memory (coalesced: 729 contiguous floats)
    #pragma unroll
    for (int i = t; i < ELEMS; i += THREADS) s[i] = sb[i];
    __syncthreads();

    // Per-cell score: nic = relu(sum_c s*w + cb - 1); m0 = clip(1-|nic|,0,1)*(-K); score = m0 - nic
    unsigned long long key = 0ull;  // safe minimum (any real score maps higher with index bits)
    if (t < CELLS) {
        float cnt = cb;
        #pragma unroll
        for (int c = 0; c < KDIM; c++) cnt = fmaf(s[c * CELLS + t], w[c], cnt);
        float nic   = fmaxf(cnt - 1.0f, 0.0f);
        float m0    = fminf(fmaxf(1.0f - fabsf(nic), 0.0f), 1.0f) * (-(float)KDIM);
        float score = m0 - nic;
        // pack: high bits = ordered score, low 7 bits = (127 - cell) so ties pick SMALLEST cell
        key = ((unsigned long long)fmap(score) << 7) | (unsigned long long)(127 - t);
    }
    keys[t] = key;
    __syncthreads();

    // max tree-reduce over 128 keys
    #pragma unroll
    for (int off = THREADS / 2; off > 0; off >>= 1) {
        if (t < off) {
            unsigned long long o = keys[t + off];
            if (o > keys[t]) keys[t] = o;
        }
        __syncthreads();
    }

    if (t == 0) {
        int cell = 127 - (int)(keys[0] & 127ull);
        // first-occurrence channel argmax at the chosen cell
        float mv = s[cell];
        int   mi = 0;
        #pragma unroll
        for (int c = 1; c < KDIM; c++) {
            float v = s[c * CELLS + cell];
            if (v > mv) { mv = v; mi = c; }
        }
        sh_cell    = cell;
        sh_midx    = mi;
        sh_mval    = mv;
        sh_cm_star = fminf(fmaxf(fmaf(mv, w[mi], cb), 0.0f), 1.0f); // cell_mask at chosen cell
        sh_cb_clip = fminf(fmaxf(cb, 0.0f), 1.0f);                  // cell_mask everywhere else
    }
    __syncthreads();

    const float ri        = rindex[b];
    const int   cell_star = sh_cell;
    const int   midx      = sh_midx;
    const float mval      = sh_mval;
    const float cm_star   = sh_cm_star;
    const float cb_clip   = sh_cb_clip;

    const size_t N = (size_t)B * ELEMS;
    float* __restrict__ out_sud = out + (size_t)b * ELEMS;
    float* __restrict__ out_rm  = out + N + (size_t)b * ELEMS;

    // Elementwise epilogue: stream recursion_mask from gmem, sudoku from smem
    #pragma unroll
    for (int e = t; e < ELEMS; e += THREADS) {
        int   c    = e / CELLS;
        int   cell = e - c * CELLS;
        float sv   = s[e];
        float rv   = rb[e];
        float ov   = (cell == cell_star && c == midx) ? mval : 0.0f;
        float cm   = (cell == cell_star) ? cm_star : cb_clip;
        float orm  = sv * cm * (1.0f - ov);                 // one_recursion_mask
        float rmo  = fmaxf(rv, fmaxf(ri * orm, (ri - 1.0f) * ov));
        out_sud[e] = sv * (1.0f - orm);
        out_rm[e]  = rmo;
    }
    if (t == 0) out[2 * N + b] = ri + 1.0f;
}

extern "C" void kernel_launch(void* const* d_in, const int* in_sizes, int n_in,
                              void* d_out, int out_size) {
    const float* sud    = (const float*)d_in[0];
    const float* rmask  = (const float*)d_in[1];
    const float* rindex = (const float*)d_in[2];
    const float* conv_w = (const float*)d_in[3];
    const float* conv_b = (const float*)d_in[4];
    float* out = (float*)d_out;
    int B = in_sizes[2];  // number of boards (recursion_index element count)

    sudoku_iterate_kernel<<<B, THREADS>>>(sud, rmask, rindex, conv_w, conv_b, out, B);
}